// round 9
// baseline (speedup 1.0000x reference)
#include <cuda_runtime.h>
#include <math.h>
#include <stdint.h>
#include <stddef.h>

// Problem dims (fixed by the dataset)
#define BD   2560      // B*D word-level sequences
#define SW   50        // word-level T
#define EW   200       // embedding
#define HH   128       // GRU hidden
#define BB   64        // batch (docs)
#define DD   40        // sentences per doc
#define GC   256       // gate cols = 2H
#define CC   128       // candidate cols = H

typedef unsigned long long ull;

// ---------------- packed fp32x2 helpers (sm_103a FFMA2 path) ----------------
__device__ __forceinline__ ull ffma2(ull a, ull b, ull c) {
    ull d;
    asm("fma.rn.f32x2 %0, %1, %2, %3;" : "=l"(d) : "l"(a), "l"(b), "l"(c));
    return d;
}
__device__ __forceinline__ ull pack2(float x, float y) {
    ull d;
    asm("mov.b64 %0, {%1, %2};" : "=l"(d) : "r"(__float_as_uint(x)), "r"(__float_as_uint(y)));
    return d;
}
__device__ __forceinline__ float2 unpack2(ull v) {
    unsigned lo, hi;
    asm("mov.b64 {%0, %1}, %2;" : "=r"(lo), "=r"(hi) : "l"(v));
    float2 r; r.x = __uint_as_float(lo); r.y = __uint_as_float(hi);
    return r;
}

// ---------------- scratch (device globals; no allocation allowed) ----------------
__device__ float g_XWg_f[(size_t)BD*SW*GC];
__device__ float g_XWc_f[(size_t)BD*SW*CC];
__device__ float g_XWg_b[(size_t)BD*SW*GC];
__device__ float g_XWc_b[(size_t)BD*SW*CC];
__device__ float g_low  [(size_t)BD*SW*GC];
__device__ float g_proj [(size_t)BD*SW*CC];
__device__ float g_sent[BD*GC];
__device__ float g_sXWg_f[BB*DD*GC];
__device__ float g_sXWc_f[BB*DD*CC];
__device__ float g_sXWg_b[BB*DD*GC];
__device__ float g_sXWc_b[BB*DD*CC];
__device__ float g_high[BB*DD*GC];
__device__ float g_docvec[BB*GC];

// ---------------- generic fp32 GEMM: C = A[MxK] @ W[KxN] + bias, optional tanh ----
__global__ void __launch_bounds__(256, 2)
sgemm_bias(const float* __restrict__ A, const float* __restrict__ W,
           const float* __restrict__ bias, float* __restrict__ C,
           int M, int N, int K, int act)
{
    __shared__ __align__(16) float As[2][16][128];
    __shared__ __align__(16) float Bs[2][16][128];
    const int tid = threadIdx.x;
    const int m0 = blockIdx.x * 128;
    const int n0 = blockIdx.y * 128;
    const int tx = tid & 15;
    const int ty = tid >> 4;

    ull acc[8][4];
#pragma unroll
    for (int i = 0; i < 8; i++)
#pragma unroll
        for (int j = 0; j < 4; j++) acc[i][j] = 0ull;

    const int nchunk = (K + 15) / 16;
    float4 la[2], lb[2];

#pragma unroll
    for (int i = 0; i < 2; i++) {
        int f4  = i * 256 + tid;
        int row = f4 >> 2;
        int kg  = (f4 & 3) * 4;
        la[i] = make_float4(0.f, 0.f, 0.f, 0.f);
        if (kg < K) la[i] = *(const float4*)(A + (size_t)(m0 + row) * K + kg);
        int kr = f4 >> 5;
        int nc = (f4 & 31) * 4;
        lb[i] = make_float4(0.f, 0.f, 0.f, 0.f);
        if (kr < K) lb[i] = *(const float4*)(W + (size_t)kr * N + n0 + nc);
    }
#pragma unroll
    for (int i = 0; i < 2; i++) {
        int f4  = i * 256 + tid;
        int row = f4 >> 2;
        int kg  = (f4 & 3) * 4;
        As[0][kg + 0][row] = la[i].x; As[0][kg + 1][row] = la[i].y;
        As[0][kg + 2][row] = la[i].z; As[0][kg + 3][row] = la[i].w;
        int kr = f4 >> 5;
        int nc = (f4 & 31) * 4;
        *(float4*)&Bs[0][kr][nc] = lb[i];
    }
    __syncthreads();

    for (int c = 0; c < nchunk; c++) {
        if (c + 1 < nchunk) {
            const int k0 = (c + 1) * 16;
#pragma unroll
            for (int i = 0; i < 2; i++) {
                int f4  = i * 256 + tid;
                int row = f4 >> 2;
                int kg  = (f4 & 3) * 4;
                la[i] = make_float4(0.f, 0.f, 0.f, 0.f);
                if (k0 + kg < K) la[i] = *(const float4*)(A + (size_t)(m0 + row) * K + k0 + kg);
                int kr = f4 >> 5;
                int nc = (f4 & 31) * 4;
                lb[i] = make_float4(0.f, 0.f, 0.f, 0.f);
                if (k0 + kr < K) lb[i] = *(const float4*)(W + (size_t)(k0 + kr) * N + n0 + nc);
            }
        }
        const int cb = c & 1;
#pragma unroll
        for (int k = 0; k < 16; k++) {
            float4 A0 = *(const float4*)&As[cb][k][ty * 8];
            float4 A1 = *(const float4*)&As[cb][k][ty * 8 + 4];
            ulonglong2 B0 = *(const ulonglong2*)&Bs[cb][k][tx * 8];
            ulonglong2 B1 = *(const ulonglong2*)&Bs[cb][k][tx * 8 + 4];
            ull ap;
            ap = pack2(A0.x, A0.x);
            acc[0][0] = ffma2(ap, B0.x, acc[0][0]); acc[0][1] = ffma2(ap, B0.y, acc[0][1]);
            acc[0][2] = ffma2(ap, B1.x, acc[0][2]); acc[0][3] = ffma2(ap, B1.y, acc[0][3]);
            ap = pack2(A0.y, A0.y);
            acc[1][0] = ffma2(ap, B0.x, acc[1][0]); acc[1][1] = ffma2(ap, B0.y, acc[1][1]);
            acc[1][2] = ffma2(ap, B1.x, acc[1][2]); acc[1][3] = ffma2(ap, B1.y, acc[1][3]);
            ap = pack2(A0.z, A0.z);
            acc[2][0] = ffma2(ap, B0.x, acc[2][0]); acc[2][1] = ffma2(ap, B0.y, acc[2][1]);
            acc[2][2] = ffma2(ap, B1.x, acc[2][2]); acc[2][3] = ffma2(ap, B1.y, acc[2][3]);
            ap = pack2(A0.w, A0.w);
            acc[3][0] = ffma2(ap, B0.x, acc[3][0]); acc[3][1] = ffma2(ap, B0.y, acc[3][1]);
            acc[3][2] = ffma2(ap, B1.x, acc[3][2]); acc[3][3] = ffma2(ap, B1.y, acc[3][3]);
            ap = pack2(A1.x, A1.x);
            acc[4][0] = ffma2(ap, B0.x, acc[4][0]); acc[4][1] = ffma2(ap, B0.y, acc[4][1]);
            acc[4][2] = ffma2(ap, B1.x, acc[4][2]); acc[4][3] = ffma2(ap, B1.y, acc[4][3]);
            ap = pack2(A1.y, A1.y);
            acc[5][0] = ffma2(ap, B0.x, acc[5][0]); acc[5][1] = ffma2(ap, B0.y, acc[5][1]);
            acc[5][2] = ffma2(ap, B1.x, acc[5][2]); acc[5][3] = ffma2(ap, B1.y, acc[5][3]);
            ap = pack2(A1.z, A1.z);
            acc[6][0] = ffma2(ap, B0.x, acc[6][0]); acc[6][1] = ffma2(ap, B0.y, acc[6][1]);
            acc[6][2] = ffma2(ap, B1.x, acc[6][2]); acc[6][3] = ffma2(ap, B1.y, acc[6][3]);
            ap = pack2(A1.w, A1.w);
            acc[7][0] = ffma2(ap, B0.x, acc[7][0]); acc[7][1] = ffma2(ap, B0.y, acc[7][1]);
            acc[7][2] = ffma2(ap, B1.x, acc[7][2]); acc[7][3] = ffma2(ap, B1.y, acc[7][3]);
        }
        if (c + 1 < nchunk) {
            const int nb = (c + 1) & 1;
#pragma unroll
            for (int i = 0; i < 2; i++) {
                int f4  = i * 256 + tid;
                int row = f4 >> 2;
                int kg  = (f4 & 3) * 4;
                As[nb][kg + 0][row] = la[i].x; As[nb][kg + 1][row] = la[i].y;
                As[nb][kg + 2][row] = la[i].z; As[nb][kg + 3][row] = la[i].w;
                int kr = f4 >> 5;
                int nc = (f4 & 31) * 4;
                *(float4*)&Bs[nb][kr][nc] = lb[i];
            }
            __syncthreads();
        }
    }

#pragma unroll
    for (int i = 0; i < 8; i++) {
        int m = m0 + ty * 8 + i;
#pragma unroll
        for (int p = 0; p < 4; p++) {
            int n = n0 + tx * 8 + p * 2;
            float2 v = unpack2(acc[i][p]);
            v.x += bias[n]; v.y += bias[n + 1];
            if (act) { v.x = tanhf(v.x); v.y = tanhf(v.y); }
            *(float2*)(C + (size_t)m * N + n) = v;
        }
    }
}

// ---------------- WORD-LEVEL BiGRU: 512 threads, split-K, resident weights -------
// kh = tid>>8 selects k-half [kh*64, kh*64+64). Each (col,seq) pair is covered by
// two threads; kh=1 writes partials to smem P, kh=0 reduces + does the epilogue.
// Thread handles gate cols {j2, j2+1, j2+128, j2+129} = (r,z) of the SAME hidden
// units, so z never leaves registers. srh overlays P (barrier-guarded).
#define WSPB 20
#define WSR  5
__global__ void __launch_bounds__(512, 1)
gru_word_kernel(
    const float* __restrict__ XWg0, const float* __restrict__ XWg1,
    const float* __restrict__ XWc0, const float* __restrict__ XWc1,
    const float* __restrict__ Wgh0, const float* __restrict__ Wgh1,
    const float* __restrict__ Wch0, const float* __restrict__ Wch1,
    const int*   __restrict__ lens,
    float* __restrict__ outp, int T)
{
    const int dir = blockIdx.y;
    const float* XWg = dir ? XWg1 : XWg0;
    const float* XWc = dir ? XWc1 : XWc0;
    const float* Wgh = dir ? Wgh1 : Wgh0;
    const float* Wch = dir ? Wch1 : Wch0;
    const int col_off = dir * CC;

    extern __shared__ float smem[];
    float* swg = smem;                 // 128*256 = 32768 floats (128 KB)
    float* swc = swg + HH * GC;        // 128*128 = 16384 floats (64 KB)
    float* sh  = swc + HH * CC;        // 20*128  = 2560 floats
    float* P   = sh + WSPB * HH;       // 20*256  = 5120 floats (gate partials)
    float* srh = P;                    // alias: r*h (first 2560 floats)
    float* Pc  = P + WSPB * HH;        // alias: candidate partials (2560 floats)
    int*   slen = (int*)(P + WSPB * GC);

    const int tid = threadIdx.x;
    const int nb  = blockIdx.x * WSPB;
    if (tid < WSPB) slen[tid] = lens[nb + tid];

    // load weights once (both matrices), zero h
    {
        const float4* src = (const float4*)Wgh;
        float4* dst = (float4*)swg;
        for (int i = tid; i < HH * GC / 4; i += 512) dst[i] = src[i];
        src = (const float4*)Wch;
        dst = (float4*)swc;
        for (int i = tid; i < HH * CC / 4; i += 512) dst[i] = src[i];
    }
    for (int i = tid; i < WSPB * HH; i += 512) sh[i] = 0.f;
    __syncthreads();

    const int kh = tid >> 8;          // k-half
    const int t2 = tid & 255;
    const int ct = t2 & 63;
    const int rt = t2 >> 6;
    const int j2 = ct * 2;            // base col (r at j2, z at j2+128)
    const int s0 = rt * WSR;
    const int kbase = kh * 64;

    float zreg[WSR][2];
    float rh[WSR][2];

    for (int t = 0; t < T; t++) {
        // ===== gate partial: acc = h[k-half] @ Wgh =====
        ull accA[WSR], accB[WSR];
#pragma unroll
        for (int s = 0; s < WSR; s++) { accA[s] = 0ull; accB[s] = 0ull; }

#pragma unroll 2
        for (int k4 = 0; k4 < 64; k4 += 4) {
            const int k = kbase + k4;
            ull wA0 = *(const ull*)(swg + (size_t)(k + 0) * GC + j2);
            ull wB0 = *(const ull*)(swg + (size_t)(k + 0) * GC + 128 + j2);
            ull wA1 = *(const ull*)(swg + (size_t)(k + 1) * GC + j2);
            ull wB1 = *(const ull*)(swg + (size_t)(k + 1) * GC + 128 + j2);
            ull wA2 = *(const ull*)(swg + (size_t)(k + 2) * GC + j2);
            ull wB2 = *(const ull*)(swg + (size_t)(k + 2) * GC + 128 + j2);
            ull wA3 = *(const ull*)(swg + (size_t)(k + 3) * GC + j2);
            ull wB3 = *(const ull*)(swg + (size_t)(k + 3) * GC + 128 + j2);
#pragma unroll
            for (int s = 0; s < WSR; s++) {
                float4 hv = *(const float4*)(sh + (s0 + s) * HH + k);
                ull ap;
                ap = pack2(hv.x, hv.x);
                accA[s] = ffma2(ap, wA0, accA[s]); accB[s] = ffma2(ap, wB0, accB[s]);
                ap = pack2(hv.y, hv.y);
                accA[s] = ffma2(ap, wA1, accA[s]); accB[s] = ffma2(ap, wB1, accB[s]);
                ap = pack2(hv.z, hv.z);
                accA[s] = ffma2(ap, wA2, accA[s]); accB[s] = ffma2(ap, wB2, accB[s]);
                ap = pack2(hv.w, hv.w);
                accA[s] = ffma2(ap, wA3, accA[s]); accB[s] = ffma2(ap, wB3, accB[s]);
            }
        }
        if (kh == 1) {
#pragma unroll
            for (int s = 0; s < WSR; s++) {
                *(ull*)(P + (size_t)(s0 + s) * GC + j2)       = accA[s];
                *(ull*)(P + (size_t)(s0 + s) * GC + 128 + j2) = accB[s];
            }
        }
        __syncthreads();

        // gate epilogue (kh==0): r,z = sigmoid(own + partner + XWg)
        if (kh == 0) {
#pragma unroll
            for (int s = 0; s < WSR; s++) {
                int sl = s0 + s;
                int n  = nb + sl;
                int L  = slen[sl];
                int te = dir ? ((t < L) ? (L - 1 - t) : t) : t;
                float2 pA = unpack2(*(const ull*)(P + (size_t)sl * GC + j2));
                float2 pB = unpack2(*(const ull*)(P + (size_t)sl * GC + 128 + j2));
                float2 aA = unpack2(accA[s]);
                float2 aB = unpack2(accB[s]);
                const float* xgp = XWg + ((size_t)n * T + te) * GC;
                float2 xgA = *(const float2*)(xgp + j2);
                float2 xgB = *(const float2*)(xgp + 128 + j2);
                float r0 = 1.f / (1.f + expf(-(aA.x + pA.x + xgA.x)));
                float r1 = 1.f / (1.f + expf(-(aA.y + pA.y + xgA.y)));
                zreg[s][0] = 1.f / (1.f + expf(-(aB.x + pB.x + xgB.x)));
                zreg[s][1] = 1.f / (1.f + expf(-(aB.y + pB.y + xgB.y)));
                float2 hv = *(const float2*)(sh + sl * HH + j2);
                rh[s][0] = r0 * hv.x;
                rh[s][1] = r1 * hv.y;
            }
        }
        __syncthreads();   // all P reads finished before srh (alias) is written
        if (kh == 0) {
#pragma unroll
            for (int s = 0; s < WSR; s++)
                *(float2*)(srh + (s0 + s) * HH + j2) = make_float2(rh[s][0], rh[s][1]);
        }
        __syncthreads();   // srh ready

        // ===== candidate partial: acc = (r*h)[k-half] @ Wch =====
        ull accC[WSR];
#pragma unroll
        for (int s = 0; s < WSR; s++) accC[s] = 0ull;

#pragma unroll 2
        for (int k4 = 0; k4 < 64; k4 += 4) {
            const int k = kbase + k4;
            ull w0 = *(const ull*)(swc + (size_t)(k + 0) * CC + j2);
            ull w1 = *(const ull*)(swc + (size_t)(k + 1) * CC + j2);
            ull w2 = *(const ull*)(swc + (size_t)(k + 2) * CC + j2);
            ull w3 = *(const ull*)(swc + (size_t)(k + 3) * CC + j2);
#pragma unroll
            for (int s = 0; s < WSR; s++) {
                float4 rv = *(const float4*)(srh + (s0 + s) * HH + k);
                accC[s] = ffma2(pack2(rv.x, rv.x), w0, accC[s]);
                accC[s] = ffma2(pack2(rv.y, rv.y), w1, accC[s]);
                accC[s] = ffma2(pack2(rv.z, rv.z), w2, accC[s]);
                accC[s] = ffma2(pack2(rv.w, rv.w), w3, accC[s]);
            }
        }
        if (kh == 1) {
#pragma unroll
            for (int s = 0; s < WSR; s++)
                *(ull*)(Pc + (size_t)(s0 + s) * CC + j2) = accC[s];
        }
        __syncthreads();

        // final epilogue (kh==0): c = tanh(sum + XWc); h' = z*h + (1-z)*c, masked
        if (kh == 0) {
#pragma unroll
            for (int s = 0; s < WSR; s++) {
                int sl = s0 + s;
                int n  = nb + sl;
                int L  = slen[sl];
                bool valid = (t < L);
                int te = dir ? (valid ? (L - 1 - t) : t) : t;
                float2 pc = unpack2(*(const ull*)(Pc + (size_t)sl * CC + j2));
                float2 ac = unpack2(accC[s]);
                float2 xc = *(const float2*)(XWc + ((size_t)n * T + te) * CC + j2);
                float c0 = tanhf(ac.x + pc.x + xc.x);
                float c1 = tanhf(ac.y + pc.y + xc.y);
                float2 hv = *(const float2*)(sh + sl * HH + j2);
                float z0 = zreg[s][0], z1 = zreg[s][1];
                float hn0 = z0 * hv.x + (1.f - z0) * c0;
                float hn1 = z1 * hv.y + (1.f - z1) * c1;
                float2 hw; hw.x = valid ? hn0 : hv.x; hw.y = valid ? hn1 : hv.y;
                *(float2*)(sh + sl * HH + j2) = hw;
                float2 ov; ov.x = valid ? hn0 : 0.f; ov.y = valid ? hn1 : 0.f;
                *(float2*)(outp + ((size_t)n * T + te) * GC + col_off + j2) = ov;
            }
        }
        __syncthreads();   // h stable + Pc consumed before next step
    }
}

// ---------------- sentence-level BiGRU (small): 256 threads, resident weights ----
template<int SPB>
__global__ void __launch_bounds__(256, 1)
gru_resident_kernel(
    const float* __restrict__ XWg0, const float* __restrict__ XWg1,
    const float* __restrict__ XWc0, const float* __restrict__ XWc1,
    const float* __restrict__ Wgh0, const float* __restrict__ Wgh1,
    const float* __restrict__ Wch0, const float* __restrict__ Wch1,
    const int*   __restrict__ lens,
    float* __restrict__ outp, int T)
{
    constexpr int SR = SPB / 4;
    const int dir = blockIdx.y;
    const float* XWg = dir ? XWg1 : XWg0;
    const float* XWc = dir ? XWc1 : XWc0;
    const float* Wgh = dir ? Wgh1 : Wgh0;
    const float* Wch = dir ? Wch1 : Wch0;
    const int col_off = dir * CC;

    extern __shared__ float smem[];
    float* swg = smem;
    float* swc = swg + HH * GC;
    float* sh  = swc + HH * CC;
    float* srh = sh  + SPB * HH;
    float* sz  = srh + SPB * HH;
    int*   slen = (int*)(sz + SPB * HH);

    const int tid = threadIdx.x;
    const int nb  = blockIdx.x * SPB;
    if (tid < SPB) slen[tid] = lens[nb + tid];

    {
        const float4* src = (const float4*)Wgh;
        float4* dst = (float4*)swg;
        for (int i = tid; i < HH * GC / 4; i += 256) dst[i] = src[i];
        src = (const float4*)Wch;
        dst = (float4*)swc;
        for (int i = tid; i < HH * CC / 4; i += 256) dst[i] = src[i];
    }
    for (int i = tid; i < SPB * HH; i += 256) sh[i] = 0.f;
    __syncthreads();

    const int ct = tid & 63, rt = tid >> 6;
    const int j0 = ct * 4;
    const int j2 = ct * 2;
    const int s0 = rt * SR;

    for (int t = 0; t < T; t++) {
        ull accg[SR][2];
#pragma unroll
        for (int s = 0; s < SR; s++) { accg[s][0] = 0ull; accg[s][1] = 0ull; }

#pragma unroll 4
        for (int kc = 0; kc < HH; kc += 4) {
            ulonglong2 w0 = *(const ulonglong2*)(swg + (size_t)(kc + 0) * GC + j0);
            ulonglong2 w1 = *(const ulonglong2*)(swg + (size_t)(kc + 1) * GC + j0);
            ulonglong2 w2 = *(const ulonglong2*)(swg + (size_t)(kc + 2) * GC + j0);
            ulonglong2 w3 = *(const ulonglong2*)(swg + (size_t)(kc + 3) * GC + j0);
#pragma unroll
            for (int s = 0; s < SR; s++) {
                float4 hv = *(const float4*)(sh + (s0 + s) * HH + kc);
                ull ap;
                ap = pack2(hv.x, hv.x);
                accg[s][0] = ffma2(ap, w0.x, accg[s][0]); accg[s][1] = ffma2(ap, w0.y, accg[s][1]);
                ap = pack2(hv.y, hv.y);
                accg[s][0] = ffma2(ap, w1.x, accg[s][0]); accg[s][1] = ffma2(ap, w1.y, accg[s][1]);
                ap = pack2(hv.z, hv.z);
                accg[s][0] = ffma2(ap, w2.x, accg[s][0]); accg[s][1] = ffma2(ap, w2.y, accg[s][1]);
                ap = pack2(hv.w, hv.w);
                accg[s][0] = ffma2(ap, w3.x, accg[s][0]); accg[s][1] = ffma2(ap, w3.y, accg[s][1]);
            }
        }

#pragma unroll
        for (int s = 0; s < SR; s++) {
            int sl = s0 + s;
            int n  = nb + sl;
            int L  = slen[sl];
            int te = dir ? ((t < L) ? (L - 1 - t) : t) : t;
            float4 xg = *(const float4*)(XWg + ((size_t)n * T + te) * GC + j0);
            float2 g01 = unpack2(accg[s][0]);
            float2 g23 = unpack2(accg[s][1]);
            float v0 = 1.f / (1.f + expf(-(g01.x + xg.x)));
            float v1 = 1.f / (1.f + expf(-(g01.y + xg.y)));
            float v2 = 1.f / (1.f + expf(-(g23.x + xg.z)));
            float v3 = 1.f / (1.f + expf(-(g23.y + xg.w)));
            if (ct < 32) {
                float4 hv = *(const float4*)(sh + sl * HH + j0);
                float4 o; o.x = v0 * hv.x; o.y = v1 * hv.y; o.z = v2 * hv.z; o.w = v3 * hv.w;
                *(float4*)(srh + sl * HH + j0) = o;
            } else {
                float4 o; o.x = v0; o.y = v1; o.z = v2; o.w = v3;
                *(float4*)(sz + sl * HH + (j0 - 128)) = o;
            }
        }
        __syncthreads();

        ull accc[SR];
#pragma unroll
        for (int s = 0; s < SR; s++) accc[s] = 0ull;

#pragma unroll 4
        for (int kc = 0; kc < HH; kc += 4) {
            ull w0 = *(const ull*)(swc + (size_t)(kc + 0) * CC + j2);
            ull w1 = *(const ull*)(swc + (size_t)(kc + 1) * CC + j2);
            ull w2 = *(const ull*)(swc + (size_t)(kc + 2) * CC + j2);
            ull w3 = *(const ull*)(swc + (size_t)(kc + 3) * CC + j2);
#pragma unroll
            for (int s = 0; s < SR; s++) {
                float4 hv = *(const float4*)(srh + (s0 + s) * HH + kc);
                accc[s] = ffma2(pack2(hv.x, hv.x), w0, accc[s]);
                accc[s] = ffma2(pack2(hv.y, hv.y), w1, accc[s]);
                accc[s] = ffma2(pack2(hv.z, hv.z), w2, accc[s]);
                accc[s] = ffma2(pack2(hv.w, hv.w), w3, accc[s]);
            }
        }

#pragma unroll
        for (int s = 0; s < SR; s++) {
            int sl = s0 + s;
            int n  = nb + sl;
            int L  = slen[sl];
            bool valid = (t < L);
            int te = dir ? (valid ? (L - 1 - t) : t) : t;
            float2 xc = *(const float2*)(XWc + ((size_t)n * T + te) * CC + j2);
            float2 cc = unpack2(accc[s]);
            float c0 = tanhf(cc.x + xc.x);
            float c1 = tanhf(cc.y + xc.y);
            float z0 = sz[sl * HH + j2], z1 = sz[sl * HH + j2 + 1];
            float h0 = sh[sl * HH + j2], h1 = sh[sl * HH + j2 + 1];
            float hn0 = z0 * h0 + (1.f - z0) * c0;
            float hn1 = z1 * h1 + (1.f - z1) * c1;
            float2 hw; hw.x = valid ? hn0 : h0; hw.y = valid ? hn1 : h1;
            *(float2*)(sh + sl * HH + j2) = hw;
            float2 ov; ov.x = valid ? hn0 : 0.f; ov.y = valid ? hn1 : 0.f;
            *(float2*)(outp + ((size_t)n * T + te) * GC + col_off + j2) = ov;
        }
        __syncthreads();
    }
}

// ---------------- attention ------------------------------------------------------
__global__ void attention_kernel(const float* __restrict__ proj,
                                 const float* __restrict__ u,
                                 const float* __restrict__ seq,
                                 float* __restrict__ vec,
                                 float* __restrict__ att_out,
                                 int N, int T)
{
    const int n = blockIdx.x;
    const int tid = threadIdx.x;
    const int warp = tid >> 5, lane = tid & 31;
    __shared__ float su[128];
    __shared__ float sc[64];
    __shared__ float red[2];
    if (tid < 128) su[tid] = u[tid];
    __syncthreads();

    for (int t = warp; t < T; t += 8) {
        const float* pr = proj + ((size_t)n * T + t) * 128;
        float p = 0.f;
#pragma unroll
        for (int i = 0; i < 4; i++) p += pr[lane + i * 32] * su[lane + i * 32];
#pragma unroll
        for (int o = 16; o > 0; o >>= 1) p += __shfl_xor_sync(0xffffffffu, p, o);
        if (lane == 0) sc[t] = p;
    }
    __syncthreads();
    if (tid == 0) {
        float m = sc[0];
        for (int t = 1; t < T; t++) m = fmaxf(m, sc[t]);
        float s = 0.f;
        for (int t = 0; t < T; t++) s += expf(sc[t] - m);
        red[0] = m; red[1] = s;
    }
    __syncthreads();
    if (tid < T) {
        float a = expf(sc[tid] - red[0]) / red[1];
        att_out[(size_t)n * T + tid] = a;
        sc[tid] = a;
    }
    __syncthreads();
    {
        int c = tid;
        float a = 0.f;
        for (int t = 0; t < T; t++) a += sc[t] * seq[((size_t)n * T + t) * 256 + c];
        vec[(size_t)n * 256 + c] = a;
    }
}

// ---------------- final ----------------------------------------------------------
__global__ void final_kernel(const float* __restrict__ docvec, const float* __restrict__ wp,
                             const float* __restrict__ bp, const int* __restrict__ y,
                             const float* __restrict__ wa_l, const float* __restrict__ ba_l,
                             const float* __restrict__ wa_h, const float* __restrict__ uw,
                             const float* __restrict__ us, float* __restrict__ out)
{
    __shared__ float slog[640];
    __shared__ float red[256];
    __shared__ float lossb[64];
    __shared__ int corr[64];
    const int tid = threadIdx.x;

    for (int idx = tid; idx < 640; idx += 256) {
        int b = idx / 10, c = idx % 10;
        float a = bp[c];
        for (int k = 0; k < 256; k++) a += docvec[b * 256 + k] * wp[k * 10 + c];
        slog[idx] = a;
    }
    __syncthreads();
    if (tid < 64) {
        int b = tid;
        float m = slog[b * 10]; int am = 0;
        for (int c = 1; c < 10; c++) { float v = slog[b * 10 + c]; if (v > m) { m = v; am = c; } }
        float s = 0.f;
        for (int c = 0; c < 10; c++) s += expf(slog[b * 10 + c] - m);
        float lse = m + logf(s);
        int yb = y[b];
        lossb[b] = lse - slog[b * 10 + yb];
        corr[b]  = (am == yb) ? 1 : 0;
        out[1 + b] = (float)am;
    }
    float r = 0.f;
    for (int i = tid; i < 256 * 128; i += 256) {
        float v = wa_l[i]; r += v * v;
        float w = wa_h[i]; r += 2.f * w * w;
    }
    for (int i = tid; i < 128; i += 256) {
        float v = ba_l[i]; r += v * v;
        float a = uw[i];   r += a * a;
        float b2 = us[i];  r += b2 * b2;
    }
    red[tid] = r;
    __syncthreads();
    for (int o = 128; o > 0; o >>= 1) { if (tid < o) red[tid] += red[tid + o]; __syncthreads(); }
    if (tid == 0) {
        float L = 0.f; int C = 0;
        for (int b = 0; b < 64; b++) { L += lossb[b]; C += corr[b]; }
        out[0]  = L / 64.f + 0.01f * red[0];
        out[65] = (float)C / 64.f;
    }
}

// =================================================================================
extern "C" void kernel_launch(void* const* d_in, const int* in_sizes, int n_in,
                              void* d_out, int out_size)
{
    (void)in_sizes; (void)out_size;
    const float* X    = (const float*)d_in[0];
    const int*   y    = (const int*)d_in[1];
    const int*   slen = (const int*)d_in[2];
    const int*   dlen = (const int*)d_in[3];
    const int wo = (n_in >= 30) ? 6 : (n_in - 24);
    const float* Wt[24];
    for (int i = 0; i < 24; i++) Wt[i] = (const float*)d_in[wo + i];
    const float *wgf_l = Wt[0],  *bgf_l = Wt[1],  *wcf_l = Wt[2],  *bcf_l = Wt[3];
    const float *wgb_l = Wt[4],  *bgb_l = Wt[5],  *wcb_l = Wt[6],  *bcb_l = Wt[7];
    const float *wa_l  = Wt[8],  *ba_l  = Wt[9];
    const float *wgf_h = Wt[10], *bgf_h = Wt[11], *wcf_h = Wt[12], *bcf_h = Wt[13];
    const float *wgb_h = Wt[14], *bgb_h = Wt[15], *wcb_h = Wt[16], *bcb_h = Wt[17];
    const float *wa_h  = Wt[18], *ba_h  = Wt[19];
    const float *uw = Wt[20], *us = Wt[21], *wp = Wt[22], *bp = Wt[23];
    float* out = (float*)d_out;

    float *XWg_f, *XWc_f, *XWg_b, *XWc_b, *low, *proj, *sent;
    float *sXWg_f, *sXWc_f, *sXWg_b, *sXWc_b, *high, *docvec;
    cudaGetSymbolAddress((void**)&XWg_f, g_XWg_f);
    cudaGetSymbolAddress((void**)&XWc_f, g_XWc_f);
    cudaGetSymbolAddress((void**)&XWg_b, g_XWg_b);
    cudaGetSymbolAddress((void**)&XWc_b, g_XWc_b);
    cudaGetSymbolAddress((void**)&low,   g_low);
    cudaGetSymbolAddress((void**)&proj,  g_proj);
    cudaGetSymbolAddress((void**)&sent,  g_sent);
    cudaGetSymbolAddress((void**)&sXWg_f, g_sXWg_f);
    cudaGetSymbolAddress((void**)&sXWc_f, g_sXWc_f);
    cudaGetSymbolAddress((void**)&sXWg_b, g_sXWg_b);
    cudaGetSymbolAddress((void**)&sXWc_b, g_sXWc_b);
    cudaGetSymbolAddress((void**)&high,  g_high);
    cudaGetSymbolAddress((void**)&docvec, g_docvec);

    // word kernel smem: weights 48K floats + sh 2560 + P 5120 + lens
    const int smem_w = (HH * GC + HH * CC + WSPB * HH + WSPB * GC) * 4 + WSPB * 4; // 227,408 B
    const int smem_s = (HH * GC + HH * CC + 3 * 4 * HH) * 4 + 4 * 4;               // 202,768 B
    cudaFuncSetAttribute(gru_word_kernel, cudaFuncAttributeMaxDynamicSharedMemorySize, smem_w);
    cudaFuncSetAttribute(gru_resident_kernel<4>, cudaFuncAttributeMaxDynamicSharedMemorySize, smem_s);

    // 1) word-level input precompute
    sgemm_bias<<<dim3(BD * SW / 128, 2), 256>>>(X, wgf_l, bgf_l, XWg_f, BD * SW, GC, EW, 0);
    sgemm_bias<<<dim3(BD * SW / 128, 1), 256>>>(X, wcf_l, bcf_l, XWc_f, BD * SW, CC, EW, 0);
    sgemm_bias<<<dim3(BD * SW / 128, 2), 256>>>(X, wgb_l, bgb_l, XWg_b, BD * SW, GC, EW, 0);
    sgemm_bias<<<dim3(BD * SW / 128, 1), 256>>>(X, wcb_l, bcb_l, XWc_b, BD * SW, CC, EW, 0);

    // 2) word-level BiGRU: split-K, 512 threads, resident weights
    gru_word_kernel<<<dim3(BD / WSPB, 2), 512, smem_w>>>(
        XWg_f, XWg_b, XWc_f, XWc_b,
        wgf_l + (size_t)EW * GC, wgb_l + (size_t)EW * GC,
        wcf_l + (size_t)EW * CC, wcb_l + (size_t)EW * CC,
        slen, low, SW);

    // 3) word attention
    sgemm_bias<<<dim3(BD * SW / 128, 1), 256>>>(low, wa_l, ba_l, proj, BD * SW, CC, GC, 1);
    attention_kernel<<<BD, 256>>>(proj, uw, low, sent, out + 66, BD, SW);

    // 4) sentence-level input precompute
    sgemm_bias<<<dim3(BB * DD / 128, 2), 256>>>(sent, wgf_h, bgf_h, sXWg_f, BB * DD, GC, GC, 0);
    sgemm_bias<<<dim3(BB * DD / 128, 1), 256>>>(sent, wcf_h, bcf_h, sXWc_f, BB * DD, CC, GC, 0);
    sgemm_bias<<<dim3(BB * DD / 128, 2), 256>>>(sent, wgb_h, bgb_h, sXWg_b, BB * DD, GC, GC, 0);
    sgemm_bias<<<dim3(BB * DD / 128, 1), 256>>>(sent, wcb_h, bcb_h, sXWc_b, BB * DD, CC, GC, 0);

    // 5) sentence-level BiGRU
    gru_resident_kernel<4><<<dim3(BB / 4, 2), 256, smem_s>>>(
        sXWg_f, sXWg_b, sXWc_f, sXWc_b,
        wgf_h + (size_t)GC * GC, wgb_h + (size_t)GC * GC,
        wcf_h + (size_t)GC * CC, wcb_h + (size_t)GC * CC,
        dlen, high, DD);

    // 6) sentence attention
    sgemm_bias<<<dim3(BB * DD / 128, 1), 256>>>(high, wa_h, ba_h, proj, BB * DD, CC, GC, 1);
    attention_kernel<<<BB, 256>>>(proj, us, high, docvec, out + 66 + BD * SW, BB, DD);

    // 7) classifier / loss / reg / predict / accuracy
    final_kernel<<<1, 256>>>(docvec, wp, bp, y, wa_l, ba_l, wa_h, uw, us, out);
}

// round 10
// speedup vs baseline: 1.6518x; 1.6518x over previous
#include <cuda_runtime.h>
#include <math.h>
#include <stdint.h>
#include <stddef.h>

// Problem dims (fixed by the dataset)
#define BD   2560      // B*D word-level sequences
#define SW   50        // word-level T
#define EW   200       // embedding
#define HH   128       // GRU hidden
#define BB   64        // batch (docs)
#define DD   40        // sentences per doc
#define GC   256       // gate cols = 2H
#define CC   128       // candidate cols = H

typedef unsigned long long ull;

// ---------------- packed fp32x2 helpers (sm_103a FFMA2 path) ----------------
__device__ __forceinline__ ull ffma2(ull a, ull b, ull c) {
    ull d;
    asm("fma.rn.f32x2 %0, %1, %2, %3;" : "=l"(d) : "l"(a), "l"(b), "l"(c));
    return d;
}
__device__ __forceinline__ ull pack2(float x, float y) {
    ull d;
    asm("mov.b64 %0, {%1, %2};" : "=l"(d) : "r"(__float_as_uint(x)), "r"(__float_as_uint(y)));
    return d;
}
__device__ __forceinline__ float2 unpack2(ull v) {
    unsigned lo, hi;
    asm("mov.b64 {%0, %1}, %2;" : "=r"(lo), "=r"(hi) : "l"(v));
    float2 r; r.x = __uint_as_float(lo); r.y = __uint_as_float(hi);
    return r;
}

// ---------------- scratch (device globals; no allocation allowed) ----------------
__device__ float g_XWg_f[(size_t)BD*SW*GC];
__device__ float g_XWc_f[(size_t)BD*SW*CC];
__device__ float g_XWg_b[(size_t)BD*SW*GC];
__device__ float g_XWc_b[(size_t)BD*SW*CC];
__device__ float g_low  [(size_t)BD*SW*GC];
__device__ float g_proj [(size_t)BD*SW*CC];
__device__ float g_sent[BD*GC];
__device__ float g_sXWg_f[BB*DD*GC];
__device__ float g_sXWc_f[BB*DD*CC];
__device__ float g_sXWg_b[BB*DD*GC];
__device__ float g_sXWc_b[BB*DD*CC];
__device__ float g_high[BB*DD*GC];
__device__ float g_docvec[BB*GC];

// ---------------- generic fp32 GEMM: C = A[MxK] @ W[KxN] + bias, optional tanh ----
__global__ void __launch_bounds__(256, 2)
sgemm_bias(const float* __restrict__ A, const float* __restrict__ W,
           const float* __restrict__ bias, float* __restrict__ C,
           int M, int N, int K, int act)
{
    __shared__ __align__(16) float As[2][16][128];
    __shared__ __align__(16) float Bs[2][16][128];
    const int tid = threadIdx.x;
    const int m0 = blockIdx.x * 128;
    const int n0 = blockIdx.y * 128;
    const int tx = tid & 15;
    const int ty = tid >> 4;

    ull acc[8][4];
#pragma unroll
    for (int i = 0; i < 8; i++)
#pragma unroll
        for (int j = 0; j < 4; j++) acc[i][j] = 0ull;

    const int nchunk = (K + 15) / 16;
    float4 la[2], lb[2];

#pragma unroll
    for (int i = 0; i < 2; i++) {
        int f4  = i * 256 + tid;
        int row = f4 >> 2;
        int kg  = (f4 & 3) * 4;
        la[i] = make_float4(0.f, 0.f, 0.f, 0.f);
        if (kg < K) la[i] = *(const float4*)(A + (size_t)(m0 + row) * K + kg);
        int kr = f4 >> 5;
        int nc = (f4 & 31) * 4;
        lb[i] = make_float4(0.f, 0.f, 0.f, 0.f);
        if (kr < K) lb[i] = *(const float4*)(W + (size_t)kr * N + n0 + nc);
    }
#pragma unroll
    for (int i = 0; i < 2; i++) {
        int f4  = i * 256 + tid;
        int row = f4 >> 2;
        int kg  = (f4 & 3) * 4;
        As[0][kg + 0][row] = la[i].x; As[0][kg + 1][row] = la[i].y;
        As[0][kg + 2][row] = la[i].z; As[0][kg + 3][row] = la[i].w;
        int kr = f4 >> 5;
        int nc = (f4 & 31) * 4;
        *(float4*)&Bs[0][kr][nc] = lb[i];
    }
    __syncthreads();

    for (int c = 0; c < nchunk; c++) {
        if (c + 1 < nchunk) {
            const int k0 = (c + 1) * 16;
#pragma unroll
            for (int i = 0; i < 2; i++) {
                int f4  = i * 256 + tid;
                int row = f4 >> 2;
                int kg  = (f4 & 3) * 4;
                la[i] = make_float4(0.f, 0.f, 0.f, 0.f);
                if (k0 + kg < K) la[i] = *(const float4*)(A + (size_t)(m0 + row) * K + k0 + kg);
                int kr = f4 >> 5;
                int nc = (f4 & 31) * 4;
                lb[i] = make_float4(0.f, 0.f, 0.f, 0.f);
                if (k0 + kr < K) lb[i] = *(const float4*)(W + (size_t)(k0 + kr) * N + n0 + nc);
            }
        }
        const int cb = c & 1;
#pragma unroll
        for (int k = 0; k < 16; k++) {
            float4 A0 = *(const float4*)&As[cb][k][ty * 8];
            float4 A1 = *(const float4*)&As[cb][k][ty * 8 + 4];
            ulonglong2 B0 = *(const ulonglong2*)&Bs[cb][k][tx * 8];
            ulonglong2 B1 = *(const ulonglong2*)&Bs[cb][k][tx * 8 + 4];
            ull ap;
            ap = pack2(A0.x, A0.x);
            acc[0][0] = ffma2(ap, B0.x, acc[0][0]); acc[0][1] = ffma2(ap, B0.y, acc[0][1]);
            acc[0][2] = ffma2(ap, B1.x, acc[0][2]); acc[0][3] = ffma2(ap, B1.y, acc[0][3]);
            ap = pack2(A0.y, A0.y);
            acc[1][0] = ffma2(ap, B0.x, acc[1][0]); acc[1][1] = ffma2(ap, B0.y, acc[1][1]);
            acc[1][2] = ffma2(ap, B1.x, acc[1][2]); acc[1][3] = ffma2(ap, B1.y, acc[1][3]);
            ap = pack2(A0.z, A0.z);
            acc[2][0] = ffma2(ap, B0.x, acc[2][0]); acc[2][1] = ffma2(ap, B0.y, acc[2][1]);
            acc[2][2] = ffma2(ap, B1.x, acc[2][2]); acc[2][3] = ffma2(ap, B1.y, acc[2][3]);
            ap = pack2(A0.w, A0.w);
            acc[3][0] = ffma2(ap, B0.x, acc[3][0]); acc[3][1] = ffma2(ap, B0.y, acc[3][1]);
            acc[3][2] = ffma2(ap, B1.x, acc[3][2]); acc[3][3] = ffma2(ap, B1.y, acc[3][3]);
            ap = pack2(A1.x, A1.x);
            acc[4][0] = ffma2(ap, B0.x, acc[4][0]); acc[4][1] = ffma2(ap, B0.y, acc[4][1]);
            acc[4][2] = ffma2(ap, B1.x, acc[4][2]); acc[4][3] = ffma2(ap, B1.y, acc[4][3]);
            ap = pack2(A1.y, A1.y);
            acc[5][0] = ffma2(ap, B0.x, acc[5][0]); acc[5][1] = ffma2(ap, B0.y, acc[5][1]);
            acc[5][2] = ffma2(ap, B1.x, acc[5][2]); acc[5][3] = ffma2(ap, B1.y, acc[5][3]);
            ap = pack2(A1.z, A1.z);
            acc[6][0] = ffma2(ap, B0.x, acc[6][0]); acc[6][1] = ffma2(ap, B0.y, acc[6][1]);
            acc[6][2] = ffma2(ap, B1.x, acc[6][2]); acc[6][3] = ffma2(ap, B1.y, acc[6][3]);
            ap = pack2(A1.w, A1.w);
            acc[7][0] = ffma2(ap, B0.x, acc[7][0]); acc[7][1] = ffma2(ap, B0.y, acc[7][1]);
            acc[7][2] = ffma2(ap, B1.x, acc[7][2]); acc[7][3] = ffma2(ap, B1.y, acc[7][3]);
        }
        if (c + 1 < nchunk) {
            const int nb = (c + 1) & 1;
#pragma unroll
            for (int i = 0; i < 2; i++) {
                int f4  = i * 256 + tid;
                int row = f4 >> 2;
                int kg  = (f4 & 3) * 4;
                As[nb][kg + 0][row] = la[i].x; As[nb][kg + 1][row] = la[i].y;
                As[nb][kg + 2][row] = la[i].z; As[nb][kg + 3][row] = la[i].w;
                int kr = f4 >> 5;
                int nc = (f4 & 31) * 4;
                *(float4*)&Bs[nb][kr][nc] = lb[i];
            }
            __syncthreads();
        }
    }

#pragma unroll
    for (int i = 0; i < 8; i++) {
        int m = m0 + ty * 8 + i;
#pragma unroll
        for (int p = 0; p < 4; p++) {
            int n = n0 + tx * 8 + p * 2;
            float2 v = unpack2(acc[i][p]);
            v.x += bias[n]; v.y += bias[n + 1];
            if (act) { v.x = tanhf(v.x); v.y = tanhf(v.y); }
            *(float2*)(C + (size_t)m * N + n) = v;
        }
    }
}

// ---------------- WORD-LEVEL BiGRU: 512 threads, resident weights ----------------
// Same layout/barrier structure as the 256-thread version (2 syncs/step), but
// 16 warps (4/SMSP) for latency coverage: 64 col-groups x 8 seq-groups, uneven
// SR pattern {3,3,3,3,2,2,2,2} covering SPB=20 sequences. XWg/XWc prefetched at
// the top of each step so the epilogue global latency hides behind the GEMMs.
#define WSPB 20
__global__ void __launch_bounds__(512, 1)
gru_word_kernel(
    const float* __restrict__ XWg0, const float* __restrict__ XWg1,
    const float* __restrict__ XWc0, const float* __restrict__ XWc1,
    const float* __restrict__ Wgh0, const float* __restrict__ Wgh1,
    const float* __restrict__ Wch0, const float* __restrict__ Wch1,
    const int*   __restrict__ lens,
    float* __restrict__ outp, int T)
{
    const int dir = blockIdx.y;
    const float* XWg = dir ? XWg1 : XWg0;
    const float* XWc = dir ? XWc1 : XWc0;
    const float* Wgh = dir ? Wgh1 : Wgh0;
    const float* Wch = dir ? Wch1 : Wch0;
    const int col_off = dir * CC;

    extern __shared__ float smem[];
    float* swg = smem;                 // 128*256 floats (128 KB)
    float* swc = swg + HH * GC;        // 128*128 floats (64 KB)
    float* sh  = swc + HH * CC;        // 20*128
    float* srh = sh  + WSPB * HH;      // 20*128
    float* sz  = srh + WSPB * HH;      // 20*128
    int*   slen = (int*)(sz + WSPB * HH);

    const int tid = threadIdx.x;
    const int nb  = blockIdx.x * WSPB;
    if (tid < WSPB) slen[tid] = lens[nb + tid];

    // load weights once, zero h
    {
        const float4* src = (const float4*)Wgh;
        float4* dst = (float4*)swg;
        for (int i = tid; i < HH * GC / 4; i += 512) dst[i] = src[i];
        src = (const float4*)Wch;
        dst = (float4*)swc;
        for (int i = tid; i < HH * CC / 4; i += 512) dst[i] = src[i];
    }
    for (int i = tid; i < WSPB * HH; i += 512) sh[i] = 0.f;
    __syncthreads();

    const int ct = tid & 63;           // 64 col groups
    const int rt = tid >> 6;           // 8 seq groups
    const int j0 = ct * 4;             // gate cols [j0, j0+4)
    const int j2 = ct * 2;             // candidate cols [j2, j2+2)
    const int srn = (rt < 4) ? 3 : 2;                         // seqs this thread
    const int s0  = (rt < 4) ? rt * 3 : 12 + (rt - 4) * 2;    // first seq

    for (int t = 0; t < T; t++) {
        // ---- prefetch this step's XWg / XWc and per-seq masks ----
        int   te_s[3]; bool val_s[3];
        float4 xg[3]; float2 xc[3];
#pragma unroll
        for (int s = 0; s < 3; s++) {
            if (s < srn) {
                int sl = s0 + s;
                int L  = slen[sl];
                bool valid = (t < L);
                int te = dir ? (valid ? (L - 1 - t) : t) : t;
                te_s[s] = te; val_s[s] = valid;
                int n = nb + sl;
                xg[s] = *(const float4*)(XWg + ((size_t)n * T + te) * GC + j0);
                xc[s] = *(const float2*)(XWc + ((size_t)n * T + te) * CC + j2);
            }
        }

        // ===== gate GEMM: acc = h @ Wgh (cols j0..j0+3) =====
        ull a0[3], a1[3];
#pragma unroll
        for (int s = 0; s < 3; s++) { a0[s] = 0ull; a1[s] = 0ull; }

#pragma unroll 4
        for (int kc = 0; kc < HH; kc += 4) {
            ulonglong2 w0 = *(const ulonglong2*)(swg + (size_t)(kc + 0) * GC + j0);
            ulonglong2 w1 = *(const ulonglong2*)(swg + (size_t)(kc + 1) * GC + j0);
            ulonglong2 w2 = *(const ulonglong2*)(swg + (size_t)(kc + 2) * GC + j0);
            ulonglong2 w3 = *(const ulonglong2*)(swg + (size_t)(kc + 3) * GC + j0);
#pragma unroll
            for (int s = 0; s < 3; s++) {
                if (s < srn) {
                    float4 hv = *(const float4*)(sh + (s0 + s) * HH + kc);
                    ull ap;
                    ap = pack2(hv.x, hv.x);
                    a0[s] = ffma2(ap, w0.x, a0[s]); a1[s] = ffma2(ap, w0.y, a1[s]);
                    ap = pack2(hv.y, hv.y);
                    a0[s] = ffma2(ap, w1.x, a0[s]); a1[s] = ffma2(ap, w1.y, a1[s]);
                    ap = pack2(hv.z, hv.z);
                    a0[s] = ffma2(ap, w2.x, a0[s]); a1[s] = ffma2(ap, w2.y, a1[s]);
                    ap = pack2(hv.w, hv.w);
                    a0[s] = ffma2(ap, w3.x, a0[s]); a1[s] = ffma2(ap, w3.y, a1[s]);
                }
            }
        }

        // gate epilogue: g = sigmoid(acc + xg); r-threads write r*h, z-threads write z
#pragma unroll
        for (int s = 0; s < 3; s++) {
            if (s < srn) {
                int sl = s0 + s;
                float2 g01 = unpack2(a0[s]);
                float2 g23 = unpack2(a1[s]);
                float v0 = 1.f / (1.f + expf(-(g01.x + xg[s].x)));
                float v1 = 1.f / (1.f + expf(-(g01.y + xg[s].y)));
                float v2 = 1.f / (1.f + expf(-(g23.x + xg[s].z)));
                float v3 = 1.f / (1.f + expf(-(g23.y + xg[s].w)));
                if (ct < 32) {
                    float4 hv = *(const float4*)(sh + sl * HH + j0);
                    float4 o; o.x = v0 * hv.x; o.y = v1 * hv.y; o.z = v2 * hv.z; o.w = v3 * hv.w;
                    *(float4*)(srh + sl * HH + j0) = o;
                } else {
                    float4 o; o.x = v0; o.y = v1; o.z = v2; o.w = v3;
                    *(float4*)(sz + sl * HH + (j0 - 128)) = o;
                }
            }
        }
        __syncthreads();

        // ===== candidate GEMM: acc = (r*h) @ Wch (cols j2, j2+1) =====
        ull c2[3];
#pragma unroll
        for (int s = 0; s < 3; s++) c2[s] = 0ull;

#pragma unroll 4
        for (int kc = 0; kc < HH; kc += 4) {
            ull w0 = *(const ull*)(swc + (size_t)(kc + 0) * CC + j2);
            ull w1 = *(const ull*)(swc + (size_t)(kc + 1) * CC + j2);
            ull w2 = *(const ull*)(swc + (size_t)(kc + 2) * CC + j2);
            ull w3 = *(const ull*)(swc + (size_t)(kc + 3) * CC + j2);
#pragma unroll
            for (int s = 0; s < 3; s++) {
                if (s < srn) {
                    float4 rv = *(const float4*)(srh + (s0 + s) * HH + kc);
                    c2[s] = ffma2(pack2(rv.x, rv.x), w0, c2[s]);
                    c2[s] = ffma2(pack2(rv.y, rv.y), w1, c2[s]);
                    c2[s] = ffma2(pack2(rv.z, rv.z), w2, c2[s]);
                    c2[s] = ffma2(pack2(rv.w, rv.w), w3, c2[s]);
                }
            }
        }

        // final epilogue: c = tanh(acc + xc); h' = z*h + (1-z)*c, masked
#pragma unroll
        for (int s = 0; s < 3; s++) {
            if (s < srn) {
                int sl = s0 + s;
                int n  = nb + sl;
                bool valid = val_s[s];
                int te = te_s[s];
                float2 cc = unpack2(c2[s]);
                float c0 = tanhf(cc.x + xc[s].x);
                float c1 = tanhf(cc.y + xc[s].y);
                float2 zv = *(const float2*)(sz + sl * HH + j2);
                float2 hv = *(const float2*)(sh + sl * HH + j2);
                float hn0 = zv.x * hv.x + (1.f - zv.x) * c0;
                float hn1 = zv.y * hv.y + (1.f - zv.y) * c1;
                float2 hw; hw.x = valid ? hn0 : hv.x; hw.y = valid ? hn1 : hv.y;
                *(float2*)(sh + sl * HH + j2) = hw;
                float2 ov; ov.x = valid ? hn0 : 0.f; ov.y = valid ? hn1 : 0.f;
                *(float2*)(outp + ((size_t)n * T + te) * GC + col_off + j2) = ov;
            }
        }
        __syncthreads();
    }
}

// ---------------- sentence-level BiGRU (small): 256 threads, resident weights ----
template<int SPB>
__global__ void __launch_bounds__(256, 1)
gru_resident_kernel(
    const float* __restrict__ XWg0, const float* __restrict__ XWg1,
    const float* __restrict__ XWc0, const float* __restrict__ XWc1,
    const float* __restrict__ Wgh0, const float* __restrict__ Wgh1,
    const float* __restrict__ Wch0, const float* __restrict__ Wch1,
    const int*   __restrict__ lens,
    float* __restrict__ outp, int T)
{
    constexpr int SR = SPB / 4;
    const int dir = blockIdx.y;
    const float* XWg = dir ? XWg1 : XWg0;
    const float* XWc = dir ? XWc1 : XWc0;
    const float* Wgh = dir ? Wgh1 : Wgh0;
    const float* Wch = dir ? Wch1 : Wch0;
    const int col_off = dir * CC;

    extern __shared__ float smem[];
    float* swg = smem;
    float* swc = swg + HH * GC;
    float* sh  = swc + HH * CC;
    float* srh = sh  + SPB * HH;
    float* sz  = srh + SPB * HH;
    int*   slen = (int*)(sz + SPB * HH);

    const int tid = threadIdx.x;
    const int nb  = blockIdx.x * SPB;
    if (tid < SPB) slen[tid] = lens[nb + tid];

    {
        const float4* src = (const float4*)Wgh;
        float4* dst = (float4*)swg;
        for (int i = tid; i < HH * GC / 4; i += 256) dst[i] = src[i];
        src = (const float4*)Wch;
        dst = (float4*)swc;
        for (int i = tid; i < HH * CC / 4; i += 256) dst[i] = src[i];
    }
    for (int i = tid; i < SPB * HH; i += 256) sh[i] = 0.f;
    __syncthreads();

    const int ct = tid & 63, rt = tid >> 6;
    const int j0 = ct * 4;
    const int j2 = ct * 2;
    const int s0 = rt * SR;

    for (int t = 0; t < T; t++) {
        ull accg[SR][2];
#pragma unroll
        for (int s = 0; s < SR; s++) { accg[s][0] = 0ull; accg[s][1] = 0ull; }

#pragma unroll 4
        for (int kc = 0; kc < HH; kc += 4) {
            ulonglong2 w0 = *(const ulonglong2*)(swg + (size_t)(kc + 0) * GC + j0);
            ulonglong2 w1 = *(const ulonglong2*)(swg + (size_t)(kc + 1) * GC + j0);
            ulonglong2 w2 = *(const ulonglong2*)(swg + (size_t)(kc + 2) * GC + j0);
            ulonglong2 w3 = *(const ulonglong2*)(swg + (size_t)(kc + 3) * GC + j0);
#pragma unroll
            for (int s = 0; s < SR; s++) {
                float4 hv = *(const float4*)(sh + (s0 + s) * HH + kc);
                ull ap;
                ap = pack2(hv.x, hv.x);
                accg[s][0] = ffma2(ap, w0.x, accg[s][0]); accg[s][1] = ffma2(ap, w0.y, accg[s][1]);
                ap = pack2(hv.y, hv.y);
                accg[s][0] = ffma2(ap, w1.x, accg[s][0]); accg[s][1] = ffma2(ap, w1.y, accg[s][1]);
                ap = pack2(hv.z, hv.z);
                accg[s][0] = ffma2(ap, w2.x, accg[s][0]); accg[s][1] = ffma2(ap, w2.y, accg[s][1]);
                ap = pack2(hv.w, hv.w);
                accg[s][0] = ffma2(ap, w3.x, accg[s][0]); accg[s][1] = ffma2(ap, w3.y, accg[s][1]);
            }
        }

#pragma unroll
        for (int s = 0; s < SR; s++) {
            int sl = s0 + s;
            int n  = nb + sl;
            int L  = slen[sl];
            int te = dir ? ((t < L) ? (L - 1 - t) : t) : t;
            float4 xg = *(const float4*)(XWg + ((size_t)n * T + te) * GC + j0);
            float2 g01 = unpack2(accg[s][0]);
            float2 g23 = unpack2(accg[s][1]);
            float v0 = 1.f / (1.f + expf(-(g01.x + xg.x)));
            float v1 = 1.f / (1.f + expf(-(g01.y + xg.y)));
            float v2 = 1.f / (1.f + expf(-(g23.x + xg.z)));
            float v3 = 1.f / (1.f + expf(-(g23.y + xg.w)));
            if (ct < 32) {
                float4 hv = *(const float4*)(sh + sl * HH + j0);
                float4 o; o.x = v0 * hv.x; o.y = v1 * hv.y; o.z = v2 * hv.z; o.w = v3 * hv.w;
                *(float4*)(srh + sl * HH + j0) = o;
            } else {
                float4 o; o.x = v0; o.y = v1; o.z = v2; o.w = v3;
                *(float4*)(sz + sl * HH + (j0 - 128)) = o;
            }
        }
        __syncthreads();

        ull accc[SR];
#pragma unroll
        for (int s = 0; s < SR; s++) accc[s] = 0ull;

#pragma unroll 4
        for (int kc = 0; kc < HH; kc += 4) {
            ull w0 = *(const ull*)(swc + (size_t)(kc + 0) * CC + j2);
            ull w1 = *(const ull*)(swc + (size_t)(kc + 1) * CC + j2);
            ull w2 = *(const ull*)(swc + (size_t)(kc + 2) * CC + j2);
            ull w3 = *(const ull*)(swc + (size_t)(kc + 3) * CC + j2);
#pragma unroll
            for (int s = 0; s < SR; s++) {
                float4 hv = *(const float4*)(srh + (s0 + s) * HH + kc);
                accc[s] = ffma2(pack2(hv.x, hv.x), w0, accc[s]);
                accc[s] = ffma2(pack2(hv.y, hv.y), w1, accc[s]);
                accc[s] = ffma2(pack2(hv.z, hv.z), w2, accc[s]);
                accc[s] = ffma2(pack2(hv.w, hv.w), w3, accc[s]);
            }
        }

#pragma unroll
        for (int s = 0; s < SR; s++) {
            int sl = s0 + s;
            int n  = nb + sl;
            int L  = slen[sl];
            bool valid = (t < L);
            int te = dir ? (valid ? (L - 1 - t) : t) : t;
            float2 xc = *(const float2*)(XWc + ((size_t)n * T + te) * CC + j2);
            float2 cc = unpack2(accc[s]);
            float c0 = tanhf(cc.x + xc.x);
            float c1 = tanhf(cc.y + xc.y);
            float z0 = sz[sl * HH + j2], z1 = sz[sl * HH + j2 + 1];
            float h0 = sh[sl * HH + j2], h1 = sh[sl * HH + j2 + 1];
            float hn0 = z0 * h0 + (1.f - z0) * c0;
            float hn1 = z1 * h1 + (1.f - z1) * c1;
            float2 hw; hw.x = valid ? hn0 : h0; hw.y = valid ? hn1 : h1;
            *(float2*)(sh + sl * HH + j2) = hw;
            float2 ov; ov.x = valid ? hn0 : 0.f; ov.y = valid ? hn1 : 0.f;
            *(float2*)(outp + ((size_t)n * T + te) * GC + col_off + j2) = ov;
        }
        __syncthreads();
    }
}

// ---------------- attention ------------------------------------------------------
__global__ void attention_kernel(const float* __restrict__ proj,
                                 const float* __restrict__ u,
                                 const float* __restrict__ seq,
                                 float* __restrict__ vec,
                                 float* __restrict__ att_out,
                                 int N, int T)
{
    const int n = blockIdx.x;
    const int tid = threadIdx.x;
    const int warp = tid >> 5, lane = tid & 31;
    __shared__ float su[128];
    __shared__ float sc[64];
    __shared__ float red[2];
    if (tid < 128) su[tid] = u[tid];
    __syncthreads();

    for (int t = warp; t < T; t += 8) {
        const float* pr = proj + ((size_t)n * T + t) * 128;
        float p = 0.f;
#pragma unroll
        for (int i = 0; i < 4; i++) p += pr[lane + i * 32] * su[lane + i * 32];
#pragma unroll
        for (int o = 16; o > 0; o >>= 1) p += __shfl_xor_sync(0xffffffffu, p, o);
        if (lane == 0) sc[t] = p;
    }
    __syncthreads();
    if (tid == 0) {
        float m = sc[0];
        for (int t = 1; t < T; t++) m = fmaxf(m, sc[t]);
        float s = 0.f;
        for (int t = 0; t < T; t++) s += expf(sc[t] - m);
        red[0] = m; red[1] = s;
    }
    __syncthreads();
    if (tid < T) {
        float a = expf(sc[tid] - red[0]) / red[1];
        att_out[(size_t)n * T + tid] = a;
        sc[tid] = a;
    }
    __syncthreads();
    {
        int c = tid;
        float a = 0.f;
        for (int t = 0; t < T; t++) a += sc[t] * seq[((size_t)n * T + t) * 256 + c];
        vec[(size_t)n * 256 + c] = a;
    }
}

// ---------------- final ----------------------------------------------------------
__global__ void final_kernel(const float* __restrict__ docvec, const float* __restrict__ wp,
                             const float* __restrict__ bp, const int* __restrict__ y,
                             const float* __restrict__ wa_l, const float* __restrict__ ba_l,
                             const float* __restrict__ wa_h, const float* __restrict__ uw,
                             const float* __restrict__ us, float* __restrict__ out)
{
    __shared__ float slog[640];
    __shared__ float red[256];
    __shared__ float lossb[64];
    __shared__ int corr[64];
    const int tid = threadIdx.x;

    for (int idx = tid; idx < 640; idx += 256) {
        int b = idx / 10, c = idx % 10;
        float a = bp[c];
        for (int k = 0; k < 256; k++) a += docvec[b * 256 + k] * wp[k * 10 + c];
        slog[idx] = a;
    }
    __syncthreads();
    if (tid < 64) {
        int b = tid;
        float m = slog[b * 10]; int am = 0;
        for (int c = 1; c < 10; c++) { float v = slog[b * 10 + c]; if (v > m) { m = v; am = c; } }
        float s = 0.f;
        for (int c = 0; c < 10; c++) s += expf(slog[b * 10 + c] - m);
        float lse = m + logf(s);
        int yb = y[b];
        lossb[b] = lse - slog[b * 10 + yb];
        corr[b]  = (am == yb) ? 1 : 0;
        out[1 + b] = (float)am;
    }
    float r = 0.f;
    for (int i = tid; i < 256 * 128; i += 256) {
        float v = wa_l[i]; r += v * v;
        float w = wa_h[i]; r += 2.f * w * w;
    }
    for (int i = tid; i < 128; i += 256) {
        float v = ba_l[i]; r += v * v;
        float a = uw[i];   r += a * a;
        float b2 = us[i];  r += b2 * b2;
    }
    red[tid] = r;
    __syncthreads();
    for (int o = 128; o > 0; o >>= 1) { if (tid < o) red[tid] += red[tid + o]; __syncthreads(); }
    if (tid == 0) {
        float L = 0.f; int C = 0;
        for (int b = 0; b < 64; b++) { L += lossb[b]; C += corr[b]; }
        out[0]  = L / 64.f + 0.01f * red[0];
        out[65] = (float)C / 64.f;
    }
}

// =================================================================================
extern "C" void kernel_launch(void* const* d_in, const int* in_sizes, int n_in,
                              void* d_out, int out_size)
{
    (void)in_sizes; (void)out_size;
    const float* X    = (const float*)d_in[0];
    const int*   y    = (const int*)d_in[1];
    const int*   slen = (const int*)d_in[2];
    const int*   dlen = (const int*)d_in[3];
    const int wo = (n_in >= 30) ? 6 : (n_in - 24);
    const float* Wt[24];
    for (int i = 0; i < 24; i++) Wt[i] = (const float*)d_in[wo + i];
    const float *wgf_l = Wt[0],  *bgf_l = Wt[1],  *wcf_l = Wt[2],  *bcf_l = Wt[3];
    const float *wgb_l = Wt[4],  *bgb_l = Wt[5],  *wcb_l = Wt[6],  *bcb_l = Wt[7];
    const float *wa_l  = Wt[8],  *ba_l  = Wt[9];
    const float *wgf_h = Wt[10], *bgf_h = Wt[11], *wcf_h = Wt[12], *bcf_h = Wt[13];
    const float *wgb_h = Wt[14], *bgb_h = Wt[15], *wcb_h = Wt[16], *bcb_h = Wt[17];
    const float *wa_h  = Wt[18], *ba_h  = Wt[19];
    const float *uw = Wt[20], *us = Wt[21], *wp = Wt[22], *bp = Wt[23];
    float* out = (float*)d_out;

    float *XWg_f, *XWc_f, *XWg_b, *XWc_b, *low, *proj, *sent;
    float *sXWg_f, *sXWc_f, *sXWg_b, *sXWc_b, *high, *docvec;
    cudaGetSymbolAddress((void**)&XWg_f, g_XWg_f);
    cudaGetSymbolAddress((void**)&XWc_f, g_XWc_f);
    cudaGetSymbolAddress((void**)&XWg_b, g_XWg_b);
    cudaGetSymbolAddress((void**)&XWc_b, g_XWc_b);
    cudaGetSymbolAddress((void**)&low,   g_low);
    cudaGetSymbolAddress((void**)&proj,  g_proj);
    cudaGetSymbolAddress((void**)&sent,  g_sent);
    cudaGetSymbolAddress((void**)&sXWg_f, g_sXWg_f);
    cudaGetSymbolAddress((void**)&sXWc_f, g_sXWc_f);
    cudaGetSymbolAddress((void**)&sXWg_b, g_sXWg_b);
    cudaGetSymbolAddress((void**)&sXWc_b, g_sXWc_b);
    cudaGetSymbolAddress((void**)&high,  g_high);
    cudaGetSymbolAddress((void**)&docvec, g_docvec);

    // dynamic smem: weights (48K floats) + 3*SPB*HH state + SPB ints
    const int smem_w = (HH * GC + HH * CC + 3 * WSPB * HH) * 4 + WSPB * 4;  // 227,408 B
    const int smem_s = (HH * GC + HH * CC + 3 * 4 * HH) * 4 + 4 * 4;        // 202,768 B
    cudaFuncSetAttribute(gru_word_kernel, cudaFuncAttributeMaxDynamicSharedMemorySize, smem_w);
    cudaFuncSetAttribute(gru_resident_kernel<4>, cudaFuncAttributeMaxDynamicSharedMemorySize, smem_s);

    // 1) word-level input precompute
    sgemm_bias<<<dim3(BD * SW / 128, 2), 256>>>(X, wgf_l, bgf_l, XWg_f, BD * SW, GC, EW, 0);
    sgemm_bias<<<dim3(BD * SW / 128, 1), 256>>>(X, wcf_l, bcf_l, XWc_f, BD * SW, CC, EW, 0);
    sgemm_bias<<<dim3(BD * SW / 128, 2), 256>>>(X, wgb_l, bgb_l, XWg_b, BD * SW, GC, EW, 0);
    sgemm_bias<<<dim3(BD * SW / 128, 1), 256>>>(X, wcb_l, bcb_l, XWc_b, BD * SW, CC, EW, 0);

    // 2) word-level BiGRU: 512 threads, resident weights, one launch
    gru_word_kernel<<<dim3(BD / WSPB, 2), 512, smem_w>>>(
        XWg_f, XWg_b, XWc_f, XWc_b,
        wgf_l + (size_t)EW * GC, wgb_l + (size_t)EW * GC,
        wcf_l + (size_t)EW * CC, wcb_l + (size_t)EW * CC,
        slen, low, SW);

    // 3) word attention
    sgemm_bias<<<dim3(BD * SW / 128, 1), 256>>>(low, wa_l, ba_l, proj, BD * SW, CC, GC, 1);
    attention_kernel<<<BD, 256>>>(proj, uw, low, sent, out + 66, BD, SW);

    // 4) sentence-level input precompute
    sgemm_bias<<<dim3(BB * DD / 128, 2), 256>>>(sent, wgf_h, bgf_h, sXWg_f, BB * DD, GC, GC, 0);
    sgemm_bias<<<dim3(BB * DD / 128, 1), 256>>>(sent, wcf_h, bcf_h, sXWc_f, BB * DD, CC, GC, 0);
    sgemm_bias<<<dim3(BB * DD / 128, 2), 256>>>(sent, wgb_h, bgb_h, sXWg_b, BB * DD, GC, GC, 0);
    sgemm_bias<<<dim3(BB * DD / 128, 1), 256>>>(sent, wcb_h, bcb_h, sXWc_b, BB * DD, CC, GC, 0);

    // 5) sentence-level BiGRU
    gru_resident_kernel<4><<<dim3(BB / 4, 2), 256, smem_s>>>(
        sXWg_f, sXWg_b, sXWc_f, sXWc_b,
        wgf_h + (size_t)GC * GC, wgb_h + (size_t)GC * GC,
        wcf_h + (size_t)GC * CC, wcb_h + (size_t)GC * CC,
        dlen, high, DD);

    // 6) sentence attention
    sgemm_bias<<<dim3(BB * DD / 128, 1), 256>>>(high, wa_h, ba_h, proj, BB * DD, CC, GC, 1);
    attention_kernel<<<BB, 256>>>(proj, us, high, docvec, out + 66 + BD * SW, BB, DD);

    // 7) classifier / loss / reg / predict / accuracy
    final_kernel<<<1, 256>>>(docvec, wp, bp, y, wa_l, ba_l, wa_h, uw, us, out);
}